// round 4
// baseline (speedup 1.0000x reference)
#include <cuda_runtime.h>
#include <cuda_fp16.h>

// Problem constants (from reference)
#define NV 100000      // vertices
#define TT 128         // temporal depth
#define NE_MAX 1600000 // edges

// ---------------- static device scratch (allocation-free) ----------------
__device__ __half g_hbuf[2][(size_t)NV * TT]; // ping-pong fp16 feature buffers (2 x 25.6MB)
__device__ int    g_deg[NV];
__device__ int    g_off[NV];
__device__ int    g_cur[NV];
__device__ int    g_srcs[NE_MAX];            // stores src*16 (uint4-row units, premultiplied)
__device__ float  g_inv[NV];
__device__ int    g_total;

// ---------------- helpers ----------------
__device__ __forceinline__ uint2 f4h2(float4 v) {
    __half2 a = __floats2half2_rn(v.x, v.y);
    __half2 b = __floats2half2_rn(v.z, v.w);
    uint2 r;
    r.x = *(unsigned*)&a;
    r.y = *(unsigned*)&b;
    return r;
}

// ---------------- input conversion fp32 -> fp16 (+ fused zeroing) ----------------
__global__ void k_cvt(const float4* __restrict__ x) {
    int i = blockIdx.x * 256 + threadIdx.x; // NV*TT/4 = 3.2M
    ((uint2*)g_hbuf[0])[i] = f4h2(x[i]);
    if (i < NV) g_deg[i] = 0;
    if (i == 0) g_total = 0;
}

// ---------------- CSR construction (scan-free) ----------------
__global__ void k_hist(const int* __restrict__ dst, int E) {
    int i = blockIdx.x * blockDim.x + threadIdx.x;
    if (i < E) atomicAdd(&g_deg[dst[i]], 1);
}

// Offsets via warp-aggregated atomic allocation. Segment order across nodes is
// nondeterministic, but grouping (and therefore per-node sums) is unchanged.
// NV=100000: last block has exactly 5 full warps active -> full-warp masks safe.
__global__ void k_alloc() {
    int i = blockIdx.x * 256 + threadIdx.x;
    if (i >= NV) return;
    int lane = threadIdx.x & 31;
    int d = g_deg[i];
    int inc = d;
    #pragma unroll
    for (int o = 1; o < 32; o <<= 1) {
        int t = __shfl_up_sync(0xffffffffu, inc, o);
        if (lane >= o) inc += t;
    }
    int base = 0;
    if (lane == 31) base = atomicAdd(&g_total, inc);
    base = __shfl_sync(0xffffffffu, base, 31);
    int off = base + inc - d;
    g_off[i] = off;
    g_cur[i] = off;
    g_inv[i] = 1.0f / (float)(d + 1); // +1 self loop
}

__global__ void k_scatter(const int* __restrict__ src, const int* __restrict__ dst, int E) {
    int i = blockIdx.x * blockDim.x + threadIdx.x;
    if (i < E) {
        int d = dst[i];
        int p = atomicAdd(&g_cur[d], 1);
        g_srcs[p] = src[i] * 16; // premultiplied: uint4-row units
    }
}

// ---------------- fused layer: mean-aggregate -> conv1d(K=9) -> relu ----------------
// conv and mean-agg commute exactly (linear; bias survives the mean).
// HALF-WARP per node: 16 lanes, each lane owns 8 consecutive t (one uint4 = 8 fp16).
// LDG.128 gathers, fp32 accumulation, 8-deep edge unroll for MLP.
__device__ __forceinline__ void acc_row(float* acc, uint4 p) {
    const __half2* h = (const __half2*)&p;
    #pragma unroll
    for (int q = 0; q < 4; q++) {
        float2 f = __half22float2(h[q]);
        acc[2 * q] += f.x; acc[2 * q + 1] += f.y;
    }
}

__global__ void __launch_bounds__(256) k_layer(
    int in_sel, int out_sel,
    const float* __restrict__ cw, const float* __restrict__ cb)
{
    const uint4* __restrict__ xin = (const uint4*)g_hbuf[in_sel];
    uint4* __restrict__ xout = (uint4*)g_hbuf[out_sel];

    int lane  = threadIdx.x & 31;
    int slane = lane & 15;
    int n = blockIdx.x * 16 + ((threadIdx.x >> 5) << 1) + (lane >> 4);

    float w[9];
    #pragma unroll
    for (int k = 0; k < 9; k++) w[k] = __ldg(cw + k);
    float bias = __ldg(cb);

    unsigned rbase = (unsigned)n * 16u + (unsigned)slane;

    float acc[8] = {0, 0, 0, 0, 0, 0, 0, 0};
    acc_row(acc, xin[rbase]); // self loop

    int jb = g_off[n];
    int deg = g_deg[n];
    int je = jb + deg;
    float inv = g_inv[n];

    int j = jb;
    for (; j + 8 <= je; j += 8) {
        uint4 p0 = xin[(unsigned)g_srcs[j]     + slane];
        uint4 p1 = xin[(unsigned)g_srcs[j + 1] + slane];
        uint4 p2 = xin[(unsigned)g_srcs[j + 2] + slane];
        uint4 p3 = xin[(unsigned)g_srcs[j + 3] + slane];
        uint4 p4 = xin[(unsigned)g_srcs[j + 4] + slane];
        uint4 p5 = xin[(unsigned)g_srcs[j + 5] + slane];
        uint4 p6 = xin[(unsigned)g_srcs[j + 6] + slane];
        uint4 p7 = xin[(unsigned)g_srcs[j + 7] + slane];
        acc_row(acc, p0); acc_row(acc, p1); acc_row(acc, p2); acc_row(acc, p3);
        acc_row(acc, p4); acc_row(acc, p5); acc_row(acc, p6); acc_row(acc, p7);
    }
    for (; j + 4 <= je; j += 4) {
        uint4 p0 = xin[(unsigned)g_srcs[j]     + slane];
        uint4 p1 = xin[(unsigned)g_srcs[j + 1] + slane];
        uint4 p2 = xin[(unsigned)g_srcs[j + 2] + slane];
        uint4 p3 = xin[(unsigned)g_srcs[j + 3] + slane];
        acc_row(acc, p0); acc_row(acc, p1); acc_row(acc, p2); acc_row(acc, p3);
    }
    for (; j < je; ++j)
        acc_row(acc, xin[(unsigned)g_srcs[j] + slane]);

    #pragma unroll
    for (int q = 0; q < 8; q++) acc[q] *= inv;

    // conv halo via width-16 shuffles
    float vv[16];
    #pragma unroll
    for (int q = 0; q < 8; q++) vv[4 + q] = acc[q];
    #pragma unroll
    for (int q = 0; q < 4; q++)
        vv[q] = __shfl_up_sync(0xffffffffu, acc[4 + q], 1, 16);
    #pragma unroll
    for (int q = 0; q < 4; q++)
        vv[12 + q] = __shfl_down_sync(0xffffffffu, acc[q], 1, 16);
    if (slane == 0)  { vv[0] = 0.f; vv[1] = 0.f; vv[2] = 0.f; vv[3] = 0.f; }
    if (slane == 15) { vv[12] = 0.f; vv[13] = 0.f; vv[14] = 0.f; vv[15] = 0.f; }

    float res[8];
    #pragma unroll
    for (int i = 0; i < 8; i++) {
        float o = bias;
        #pragma unroll
        for (int k = 0; k < 9; k++) o = fmaf(vv[i + k], w[k], o); // cross-correlation
        res[i] = fmaxf(o, 0.0f);
    }

    uint4 outp;
    unsigned* op = (unsigned*)&outp;
    #pragma unroll
    for (int q = 0; q < 4; q++) {
        __half2 hh = __floats2half2_rn(res[2 * q], res[2 * q + 1]);
        op[q] = *(unsigned*)&hh;
    }
    xout[rbase] = outp;
}

// ---------------- final projection ----------------
// x.reshape(T,N) on row-major [N,T] is a flat reinterpretation:
// out[t,c] = b[c] + sum_n hflat[t*N+n] * W[c*N+n]; both contiguous in n.
#define TTILE 16
#define NCHF 16
__global__ void k_init_out(const float* __restrict__ bo, float* __restrict__ out) {
    int i = threadIdx.x; // 384 = TT*3
    out[i] = __ldg(bo + (i % 3));
}

__global__ void __launch_bounds__(512) k_final(
    const float* __restrict__ W, float* __restrict__ out)
{
    const __half* __restrict__ h = g_hbuf[1];
    int t0 = blockIdx.x * TTILE;
    const int nper = NV / NCHF; // 6250
    int n0 = blockIdx.y * nper;

    float acc[TTILE][3];
    #pragma unroll
    for (int t = 0; t < TTILE; t++)
        #pragma unroll
        for (int c = 0; c < 3; c++) acc[t][c] = 0.f;

    for (int n = n0 + threadIdx.x; n < n0 + nper; n += 512) {
        float w0 = __ldg(W + n);
        float w1 = __ldg(W + NV + n);
        float w2 = __ldg(W + 2 * NV + n);
        #pragma unroll
        for (int t = 0; t < TTILE; t++) {
            float v = __half2float(h[(size_t)(t0 + t) * NV + n]);
            acc[t][0] = fmaf(v, w0, acc[t][0]);
            acc[t][1] = fmaf(v, w1, acc[t][1]);
            acc[t][2] = fmaf(v, w2, acc[t][2]);
        }
    }

    #pragma unroll
    for (int t = 0; t < TTILE; t++)
        #pragma unroll
        for (int c = 0; c < 3; c++)
            #pragma unroll
            for (int o = 16; o; o >>= 1)
                acc[t][c] += __shfl_down_sync(0xffffffffu, acc[t][c], o);

    __shared__ float sh[16][TTILE][3];
    int lane = threadIdx.x & 31, wid = threadIdx.x >> 5;
    if (lane == 0)
        #pragma unroll
        for (int t = 0; t < TTILE; t++)
            #pragma unroll
            for (int c = 0; c < 3; c++) sh[wid][t][c] = acc[t][c];
    __syncthreads();
    // 48 outputs per block: first 48 threads
    if (threadIdx.x < TTILE * 3) {
        int t = threadIdx.x / 3, c = threadIdx.x % 3;
        float s = 0.f;
        #pragma unroll
        for (int wgi = 0; wgi < 16; wgi++) s += sh[wgi][t][c];
        atomicAdd(&out[(t0 + t) * 3 + c], s);
    }
}

// ---------------- launch ----------------
extern "C" void kernel_launch(void* const* d_in, const int* in_sizes, int n_in,
                              void* d_out, int out_size)
{
    const float* x  = (const float*)d_in[0];
    const int*   ei = (const int*)d_in[1];
    const float* cw = (const float*)d_in[2]; // [L,1,1,K]
    const float* cb = (const float*)d_in[3]; // [L,1]
    const float* Wo = (const float*)d_in[4]; // [3,N]
    const float* bo = (const float*)d_in[5]; // [3]
    float* out = (float*)d_out;

    int E = in_sizes[1] / 2;
    const int* src = ei;
    const int* dst = ei + E;

    // input fp32 -> fp16 (+ zero deg/total)
    k_cvt<<<NV * TT / 4 / 256, 256>>>((const float4*)x);

    // CSR by destination: hist -> atomic offset alloc -> scatter (no scans)
    k_hist<<<(E + 255) / 256, 256>>>(dst, E);
    k_alloc<<<(NV + 255) / 256, 256>>>();
    k_scatter<<<(E + 255) / 256, 256>>>(src, dst, E);

    // 3 fused layers: agg -> conv -> relu, ping-pong fp16 buffers
    k_layer<<<NV / 16, 256>>>(0, 1, cw + 0, cb + 0);
    k_layer<<<NV / 16, 256>>>(1, 0, cw + 9, cb + 1);
    k_layer<<<NV / 16, 256>>>(0, 1, cw + 18, cb + 2);

    // final [T,3] projection
    k_init_out<<<1, TT * 3>>>(bo, out);
    k_final<<<dim3(TT / TTILE, NCHF), 512>>>(Wo, out);
}

// round 5
// speedup vs baseline: 1.1193x; 1.1193x over previous
#include <cuda_runtime.h>
#include <cuda_fp16.h>

// Problem constants (from reference)
#define NV 100000      // vertices
#define TT 128         // temporal depth
#define NE_MAX 1600000 // edges

// ---------------- static device scratch (allocation-free) ----------------
__device__ __half g_hbuf[2][(size_t)NV * TT]; // ping-pong fp16 feature buffers (2 x 25.6MB)
__device__ int    g_deg[NV];
__device__ int    g_off[NV];
__device__ int    g_cur[NV];
__device__ int    g_srcs[NE_MAX];            // stores src*16 (uint4-row units, premultiplied)
__device__ float  g_inv[NV];
__device__ int    g_total;

// ---------------- helpers ----------------
__device__ __forceinline__ uint2 f4h2(float4 v) {
    __half2 a = __floats2half2_rn(v.x, v.y);
    __half2 b = __floats2half2_rn(v.z, v.w);
    uint2 r;
    r.x = *(unsigned*)&a;
    r.y = *(unsigned*)&b;
    return r;
}

// ---------------- input conversion fp32 -> fp16 (+ fused zeroing) ----------------
__global__ void k_cvt(const float4* __restrict__ x) {
    int i = blockIdx.x * 256 + threadIdx.x; // NV*TT/4 = 3.2M
    ((uint2*)g_hbuf[0])[i] = f4h2(x[i]);
    if (i < NV) g_deg[i] = 0;
    if (i == 0) g_total = 0;
}

// ---------------- CSR construction (scan-free) ----------------
// 4 edges per thread -> 4 independent atomic chains in flight (MLP=4).
__global__ void k_hist(const int* __restrict__ dst, int E) {
    int i = (blockIdx.x * 256 + threadIdx.x) * 4;
    if (i + 4 <= E) {
        int d0 = dst[i], d1 = dst[i + 1], d2 = dst[i + 2], d3 = dst[i + 3];
        atomicAdd(&g_deg[d0], 1);
        atomicAdd(&g_deg[d1], 1);
        atomicAdd(&g_deg[d2], 1);
        atomicAdd(&g_deg[d3], 1);
    } else {
        for (; i < E; ++i) atomicAdd(&g_deg[dst[i]], 1);
    }
}

// Offsets via warp-aggregated atomic allocation. Segment order across nodes is
// nondeterministic, but grouping (and therefore per-node sums) is unchanged.
__global__ void k_alloc() {
    int i = blockIdx.x * 256 + threadIdx.x;
    if (i >= NV) return;
    int lane = threadIdx.x & 31;
    int d = g_deg[i];
    int inc = d;
    #pragma unroll
    for (int o = 1; o < 32; o <<= 1) {
        int t = __shfl_up_sync(0xffffffffu, inc, o);
        if (lane >= o) inc += t;
    }
    int base = 0;
    if (lane == 31) base = atomicAdd(&g_total, inc);
    base = __shfl_sync(0xffffffffu, base, 31);
    int off = base + inc - d;
    g_off[i] = off;
    g_cur[i] = off;
    g_inv[i] = 1.0f / (float)(d + 1); // +1 self loop
}

__global__ void k_scatter(const int* __restrict__ src, const int* __restrict__ dst, int E) {
    int i = (blockIdx.x * 256 + threadIdx.x) * 4;
    if (i + 4 <= E) {
        int d0 = dst[i], d1 = dst[i + 1], d2 = dst[i + 2], d3 = dst[i + 3];
        int s0 = src[i], s1 = src[i + 1], s2 = src[i + 2], s3 = src[i + 3];
        int p0 = atomicAdd(&g_cur[d0], 1);
        int p1 = atomicAdd(&g_cur[d1], 1);
        int p2 = atomicAdd(&g_cur[d2], 1);
        int p3 = atomicAdd(&g_cur[d3], 1);
        g_srcs[p0] = s0 * 16; // premultiplied: uint4-row units
        g_srcs[p1] = s1 * 16;
        g_srcs[p2] = s2 * 16;
        g_srcs[p3] = s3 * 16;
    } else {
        for (; i < E; ++i) {
            int p = atomicAdd(&g_cur[dst[i]], 1);
            g_srcs[p] = src[i] * 16;
        }
    }
}

// ---------------- fused layer: mean-aggregate -> conv1d(K=9) -> relu ----------------
// conv and mean-agg commute exactly (linear; bias survives the mean).
// HALF-WARP per node: 16 lanes, each lane owns 8 consecutive t (one uint4 = 8 fp16).
// LDG.128 gathers, fp32 accumulation, 4-deep edge unroll (8-deep regressed: reg pressure).
__global__ void __launch_bounds__(256) k_layer(
    int in_sel, int out_sel,
    const float* __restrict__ cw, const float* __restrict__ cb)
{
    const uint4* __restrict__ xin = (const uint4*)g_hbuf[in_sel];
    uint4* __restrict__ xout = (uint4*)g_hbuf[out_sel];

    int lane  = threadIdx.x & 31;
    int slane = lane & 15;
    int n = blockIdx.x * 16 + ((threadIdx.x >> 5) << 1) + (lane >> 4);

    float w[9];
    #pragma unroll
    for (int k = 0; k < 9; k++) w[k] = __ldg(cw + k);
    float bias = __ldg(cb);

    unsigned rbase = (unsigned)n * 16u + (unsigned)slane;

    float acc[8];
    { // self loop
        uint4 p = xin[rbase];
        const __half2* h = (const __half2*)&p;
        #pragma unroll
        for (int q = 0; q < 4; q++) {
            float2 f = __half22float2(h[q]);
            acc[2 * q] = f.x; acc[2 * q + 1] = f.y;
        }
    }

    int jb = g_off[n];
    int je = jb + g_deg[n];
    float inv = g_inv[n];

    int j = jb;
    for (; j + 4 <= je; j += 4) {
        unsigned s0 = (unsigned)g_srcs[j];
        unsigned s1 = (unsigned)g_srcs[j + 1];
        unsigned s2 = (unsigned)g_srcs[j + 2];
        unsigned s3 = (unsigned)g_srcs[j + 3];
        uint4 p0 = xin[s0 + slane];
        uint4 p1 = xin[s1 + slane];
        uint4 p2 = xin[s2 + slane];
        uint4 p3 = xin[s3 + slane];
        const __half2* h0 = (const __half2*)&p0;
        const __half2* h1 = (const __half2*)&p1;
        const __half2* h2 = (const __half2*)&p2;
        const __half2* h3 = (const __half2*)&p3;
        #pragma unroll
        for (int q = 0; q < 4; q++) {
            float2 f0 = __half22float2(h0[q]);
            float2 f1 = __half22float2(h1[q]);
            float2 f2 = __half22float2(h2[q]);
            float2 f3 = __half22float2(h3[q]);
            acc[2 * q]     += (f0.x + f1.x) + (f2.x + f3.x);
            acc[2 * q + 1] += (f0.y + f1.y) + (f2.y + f3.y);
        }
    }
    for (; j < je; ++j) {
        uint4 p = xin[(unsigned)g_srcs[j] + slane];
        const __half2* h = (const __half2*)&p;
        #pragma unroll
        for (int q = 0; q < 4; q++) {
            float2 f = __half22float2(h[q]);
            acc[2 * q] += f.x; acc[2 * q + 1] += f.y;
        }
    }

    #pragma unroll
    for (int q = 0; q < 8; q++) acc[q] *= inv;

    // conv halo via width-16 shuffles
    float vv[16];
    #pragma unroll
    for (int q = 0; q < 8; q++) vv[4 + q] = acc[q];
    #pragma unroll
    for (int q = 0; q < 4; q++)
        vv[q] = __shfl_up_sync(0xffffffffu, acc[4 + q], 1, 16);
    #pragma unroll
    for (int q = 0; q < 4; q++)
        vv[12 + q] = __shfl_down_sync(0xffffffffu, acc[q], 1, 16);
    if (slane == 0)  { vv[0] = 0.f; vv[1] = 0.f; vv[2] = 0.f; vv[3] = 0.f; }
    if (slane == 15) { vv[12] = 0.f; vv[13] = 0.f; vv[14] = 0.f; vv[15] = 0.f; }

    float res[8];
    #pragma unroll
    for (int i = 0; i < 8; i++) {
        float o = bias;
        #pragma unroll
        for (int k = 0; k < 9; k++) o = fmaf(vv[i + k], w[k], o); // cross-correlation
        res[i] = fmaxf(o, 0.0f);
    }

    uint4 outp;
    unsigned* op = (unsigned*)&outp;
    #pragma unroll
    for (int q = 0; q < 4; q++) {
        __half2 hh = __floats2half2_rn(res[2 * q], res[2 * q + 1]);
        op[q] = *(unsigned*)&hh;
    }
    xout[rbase] = outp;
}

// ---------------- final projection ----------------
// x.reshape(T,N) on row-major [N,T] is a flat reinterpretation:
// out[t,c] = b[c] + sum_n hflat[t*N+n] * W[c*N+n]; both contiguous in n.
#define TTILE 8
#define NCHF 8
__global__ void k_init_out(const float* __restrict__ bo, float* __restrict__ out) {
    int i = threadIdx.x; // 384 = TT*3
    out[i] = __ldg(bo + (i % 3));
}

__global__ void __launch_bounds__(512) k_final(
    const float* __restrict__ W, float* __restrict__ out)
{
    const __half* __restrict__ h = g_hbuf[1];
    int t0 = blockIdx.x * TTILE;
    const int nper = NV / NCHF; // 12500
    int n0 = blockIdx.y * nper;

    float acc[TTILE][3];
    #pragma unroll
    for (int t = 0; t < TTILE; t++)
        #pragma unroll
        for (int c = 0; c < 3; c++) acc[t][c] = 0.f;

    for (int n = n0 + threadIdx.x; n < n0 + nper; n += 512) {
        float w0 = __ldg(W + n);
        float w1 = __ldg(W + NV + n);
        float w2 = __ldg(W + 2 * NV + n);
        #pragma unroll
        for (int t = 0; t < TTILE; t++) {
            float v = __half2float(h[(size_t)(t0 + t) * NV + n]);
            acc[t][0] = fmaf(v, w0, acc[t][0]);
            acc[t][1] = fmaf(v, w1, acc[t][1]);
            acc[t][2] = fmaf(v, w2, acc[t][2]);
        }
    }

    #pragma unroll
    for (int t = 0; t < TTILE; t++)
        #pragma unroll
        for (int c = 0; c < 3; c++)
            #pragma unroll
            for (int o = 16; o; o >>= 1)
                acc[t][c] += __shfl_down_sync(0xffffffffu, acc[t][c], o);

    __shared__ float sh[16][TTILE][3];
    int lane = threadIdx.x & 31, wid = threadIdx.x >> 5;
    if (lane == 0)
        #pragma unroll
        for (int t = 0; t < TTILE; t++)
            #pragma unroll
            for (int c = 0; c < 3; c++) sh[wid][t][c] = acc[t][c];
    __syncthreads();
    // 24 outputs per block: lanes 0..23 of warp 0
    if (wid == 0 && lane < TTILE * 3) {
        int t = lane / 3, c = lane % 3;
        float s = 0.f;
        #pragma unroll
        for (int wgi = 0; wgi < 16; wgi++) s += sh[wgi][t][c];
        atomicAdd(&out[(t0 + t) * 3 + c], s);
    }
}

// ---------------- launch ----------------
extern "C" void kernel_launch(void* const* d_in, const int* in_sizes, int n_in,
                              void* d_out, int out_size)
{
    const float* x  = (const float*)d_in[0];
    const int*   ei = (const int*)d_in[1];
    const float* cw = (const float*)d_in[2]; // [L,1,1,K]
    const float* cb = (const float*)d_in[3]; // [L,1]
    const float* Wo = (const float*)d_in[4]; // [3,N]
    const float* bo = (const float*)d_in[5]; // [3]
    float* out = (float*)d_out;

    int E = in_sizes[1] / 2;
    const int* src = ei;
    const int* dst = ei + E;

    // input fp32 -> fp16 (+ zero deg/total)
    k_cvt<<<NV * TT / 4 / 256, 256>>>((const float4*)x);

    // CSR by destination: hist -> atomic offset alloc -> scatter (no scans)
    int eb = (E / 4 + 255) / 256 + 1;
    k_hist<<<eb, 256>>>(dst, E);
    k_alloc<<<(NV + 255) / 256, 256>>>();
    k_scatter<<<eb, 256>>>(src, dst, E);

    // 3 fused layers: agg -> conv -> relu, ping-pong fp16 buffers
    k_layer<<<NV / 16, 256>>>(0, 1, cw + 0, cb + 0);
    k_layer<<<NV / 16, 256>>>(1, 0, cw + 9, cb + 1);
    k_layer<<<NV / 16, 256>>>(0, 1, cw + 18, cb + 2);

    // final [T,3] projection
    k_init_out<<<1, TT * 3>>>(bo, out);
    k_final<<<dim3(TT / TTILE, NCHF), 512>>>(Wo, out);
}